// round 5
// baseline (speedup 1.0000x reference)
#include <cuda_runtime.h>
#include <math.h>

// ----------------------------------------------------------------------------
// UnifiedKAN: 2-layer KAN with learned-knot cubic B-splines.
// Splines = piecewise cubics over 6 real intervals. Setup (20 blocks, fp32)
// fits centered-monomial cubics AND builds a 512-bucket uniform index LUT per
// spline (domain [-1,1] shared by all splines). Main kernel: bucket computed
// once per input value; per spline: LUT byte + knot-correction compare ->
// interval idx -> LDS.128 coefs + LDS center + Horner.
// ----------------------------------------------------------------------------

#define GRID_ 5
#define IN_ 4
#define HID_ 4
#define NSPL 20
#define NBUCK 512
// Per-spline record (40 floats, 160B):
// [0..4] interior knots K0..K4, [5] = 2.0f sentinel, [6..7] pad,
// [8..13] interval centers m[0..5], [14..15] pad, [16+4j..] coefs c0..c3.
#define SPL_STRIDE 40
#define PARAMS_W 800   // softmax weights (8 floats)
#define PARAMS_B 808   // base offset scalar
#define PARAMS_N 809

__device__ float g_params[832];
__device__ unsigned char g_lut[NSPL * NBUCK];   // 10240 B

// Reference float32 Cox-de Boor (truncated to first 8 basis fns), denominators
// replaced by precomputed reciprocals rc[] (0 when den<=1e-8).
__device__ __forceinline__ float eval_ref_spline(float x, const float* kn /*13*/,
                                                 const float* rc /*33*/,
                                                 const float* cf /*8*/) {
    float b[12];
    #pragma unroll
    for (int j = 0; j < 12; j++)
        b[j] = (x >= kn[j] && x < kn[j + 1]) ? 1.0f : 0.0f;
    if (x == kn[12]) b[11] += 1.0f;
    const int off[4] = {0, 0, 12, 23};
    #pragma unroll
    for (int d = 1; d <= 3; d++) {
        int n = 12 - d;
        const float* r = rc + off[d];
        #pragma unroll
        for (int j = 0; j < 11; j++) {
            if (j >= n) break;
            float t1 = (x - kn[j]) * r[j] * b[j];
            float t2 = (kn[d + 1 + j] - x) * r[j + 1] * b[j + 1];
            b[j] = t1 + t2;  // in-place ascending: b[j+1] still old value
        }
    }
    float s = 0.0f;
    #pragma unroll
    for (int j = 0; j < 8; j++) s += b[j] * cf[j];
    return s;
}

// One block per spline, 32 threads.
__global__ void kan_setup_kernel(const float* __restrict__ l1_coeffs,
                                 const float* __restrict__ l1_kd,
                                 const float* __restrict__ op_alpha,
                                 const float* __restrict__ gumbel,
                                 const float* __restrict__ l2_coeffs,
                                 const float* __restrict__ l2_kd,
                                 const float* __restrict__ base_offset) {
    __shared__ float s_rc[33];
    __shared__ float s_fv[24];   // [6 intervals][4 nodes]

    int s = blockIdx.x;
    int lane = threadIdx.x;
    const float* kd = (s < 16) ? (l1_kd + s * (GRID_ + 1)) : (l2_kd + (s - 16) * (GRID_ + 1));
    const float* cf = (s < 16) ? (l1_coeffs + s * 8) : (l2_coeffs + (s - 16) * 8);

    // Every lane redundantly computes the 13-knot vector (lockstep, cheap).
    float d[GRID_ + 1];
    float dsum = 0.0f;
    #pragma unroll
    for (int k = 0; k < GRID_ + 1; k++) {
        float v = kd[k];
        d[k] = fmaxf(v, 0.0f) + log1pf(expf(-fabsf(v)));  // stable softplus
        dsum += d[k];
    }
    float kn[13];
    kn[0] = kn[1] = kn[2] = kn[3] = -1.0f;
    float cum = 0.0f;
    #pragma unroll
    for (int k = 0; k < 5; k++) {
        cum += d[k] / dsum * 2.0f;
        kn[4 + k] = -1.0f + cum;
    }
    kn[9] = kn[10] = kn[11] = kn[12] = 1.0f;

    // Bucket LUT: base interval index of each bucket's start point.
    // interior knots are kn[4..8].
    for (int t = lane; t < NBUCK; t += 32) {
        float lo = -1.0f + (float)t * (2.0f / (float)NBUCK);
        int b = (lo >= kn[4]) + (lo >= kn[5]) + (lo >= kn[6]) + (lo >= kn[7]) + (lo >= kn[8]);
        g_lut[s * NBUCK + t] = (unsigned char)b;
    }

    // Reciprocals of the 33 knot-difference denominators (masked to 0).
    for (int t = lane; t < 33; t += 32) {
        int dd, j;
        if (t < 12)      { dd = 1; j = t; }
        else if (t < 23) { dd = 2; j = t - 12; }
        else             { dd = 3; j = t - 23; }
        float den = kn[dd + j] - kn[j];
        s_rc[t] = (den > 1e-8f) ? 1.0f / den : 0.0f;
    }
    __syncthreads();

    // Lanes 0..23: each samples ONE node of ONE interval.
    if (lane < 24) {
        int j = lane >> 2, k = lane & 3;
        float lo = kn[3 + j], hi = kn[4 + j];
        float u = lo + (hi - lo) * (0.125f + 0.25f * (float)k);
        s_fv[lane] = eval_ref_spline(u, kn, s_rc, cf);
    } else if (s == 0) {
        int h = lane - 24;
        if (h < HID_) {
            float a0 = op_alpha[h * 2 + 0] + gumbel[h * 2 + 0];
            float a1 = op_alpha[h * 2 + 1] + gumbel[h * 2 + 1];
            float mx = fmaxf(a0, a1);
            float e0 = expf(a0 - mx), e1 = expf(a1 - mx);
            float inv = 1.0f / (e0 + e1);
            g_params[PARAMS_W + h * 2 + 0] = e0 * inv;
            g_params[PARAMS_W + h * 2 + 1] = e1 * inv;
        }
        if (lane == 28) g_params[PARAMS_B] = base_offset[0];
    }
    __syncthreads();

    float* P = g_params + s * SPL_STRIDE;
    if (lane < 5) P[lane] = kn[4 + lane];  // interior knots
    if (lane == 5) { P[5] = 2.0f; P[6] = 2.0f; P[7] = 2.0f; }  // sentinels

    // Lanes 0..5: fit exact cubic on interval j via fp32 divided differences.
    // Nodes equispaced in s=(x-m)/w at {-3/8,-1/8,1/8,3/8}; one reciprocal rw.
    if (lane < 6) {
        int j = lane;
        float lo = kn[3 + j], hi = kn[4 + j];
        float w = hi - lo;
        float m = lo + 0.5f * w;
        float rw = 1.0f / w;
        float f0 = s_fv[j * 4 + 0], f1 = s_fv[j * 4 + 1];
        float f2 = s_fv[j * 4 + 2], f3 = s_fv[j * 4 + 3];
        float d1a = 4.0f * (f1 - f0);
        float d1b = 4.0f * (f2 - f1);
        float d1c = 4.0f * (f3 - f2);
        float d2a = 2.0f * (d1b - d1a);
        float d2b = 2.0f * (d1c - d1b);
        float d3  = (4.0f / 3.0f) * (d2b - d2a);
        // Expand Newton form to monomial in s (nodes -3/8,-1/8,1/8):
        float p0 = d3, p1 = 0.0f, p2 = 0.0f, p3 = 0.0f;
        const float nodes[3] = {0.125f, -0.125f, -0.375f};
        const float adds[3]  = {d2a, d1a, f0};
        #pragma unroll
        for (int st = 0; st < 3; st++) {
            float vv = nodes[st];
            float q3 = p2, q2 = p1, q1 = p0;
            float q0 = adds[st] - vv * p0;
            q1 -= vv * p1; q2 -= vv * p2; q3 -= vv * p3;
            p0 = q0; p1 = q1; p2 = q2; p3 = q3;
        }
        float rw2 = rw * rw;
        P[8 + j] = m;
        P[16 + 4 * j + 0] = p0;
        P[16 + 4 * j + 1] = p1 * rw;
        P[16 + 4 * j + 2] = p2 * rw2;
        P[16 + 4 * j + 3] = p3 * rw2 * rw;
    }
}

// Evaluate one spline given the shared-bucket index (exact interval via one
// knot-correction compare).
__device__ __forceinline__ float eval_spline_lut(float x, int bucket,
                                                 const unsigned char* lut,
                                                 const float* sp) {
    int b = lut[bucket];              // LDS.U8
    float K = sp[b];                  // next interior knot (sentinel 2.0 if none)
    int idx = b + (x >= K);
    float m = sp[8 + idx];            // LDS.32
    float4 c = *reinterpret_cast<const float4*>(sp + 16 + 4 * idx);  // LDS.128
    float t = x - m;
    return fmaf(fmaf(fmaf(c.w, t, c.z), t, c.y), t, c.x);
}

__device__ __forceinline__ int bucket_of(float x) {
    float f = fminf(fmaf(x, (float)(NBUCK / 2), (float)(NBUCK / 2)), (float)(NBUCK - 1));
    return (int)f;
}

__global__ void __launch_bounds__(256) kan_main_kernel(const float4* __restrict__ x,
                                                       float* __restrict__ out, int n) {
    __shared__ __align__(16) unsigned char s_lut[NSPL * NBUCK];  // 10240 B
    __shared__ __align__(16) float sp[832];
    {
        const int4* src = reinterpret_cast<const int4*>(g_lut);
        int4* dst = reinterpret_cast<int4*>(s_lut);
        for (int k = threadIdx.x; k < (NSPL * NBUCK) / 16; k += blockDim.x)
            dst[k] = src[k];
        for (int k = threadIdx.x; k < PARAMS_N; k += blockDim.x)
            sp[k] = g_params[k];
    }
    __syncthreads();

    int i0 = blockIdx.x * blockDim.x + threadIdx.x;
    if (i0 >= n) return;

    float4 xv = x[i0];
    float xi[4] = {xv.x, xv.y, xv.z, xv.w};
    int bx[4];
    #pragma unroll
    for (int i = 0; i < 4; i++) bx[i] = bucket_of(xi[i]);

    float acc = sp[PARAMS_B];
    #pragma unroll
    for (int h = 0; h < HID_; h++) {
        float sum = 0.0f, prod = 1.0f;
        #pragma unroll
        for (int i = 0; i < IN_; i++) {
            int spl = h * IN_ + i;
            float v = eval_spline_lut(xi[i], bx[i], s_lut + spl * NBUCK,
                                      sp + spl * SPL_STRIDE);
            sum += v;
            prod *= fminf(fmaxf(v, -5.0f), 5.0f);
        }
        float hid = sp[PARAMS_W + h * 2 + 0] * sum + sp[PARAMS_W + h * 2 + 1] * prod;
        if (hid >= -1.0f && hid <= 1.0f) {
            int spl = 16 + h;
            acc += eval_spline_lut(hid, bucket_of(hid), s_lut + spl * NBUCK,
                                   sp + spl * SPL_STRIDE);
        }
    }
    out[i0] = acc;
}

extern "C" void kernel_launch(void* const* d_in, const int* in_sizes, int n_in,
                              void* d_out, int out_size) {
    const float* x          = (const float*)d_in[0];
    const float* l1_coeffs  = (const float*)d_in[1];
    const float* l1_kd      = (const float*)d_in[2];
    const float* op_alpha   = (const float*)d_in[3];
    const float* gumbel     = (const float*)d_in[4];
    const float* l2_coeffs  = (const float*)d_in[5];
    const float* l2_kd      = (const float*)d_in[6];
    const float* base_off   = (const float*)d_in[7];
    float* out = (float*)d_out;

    int n = in_sizes[0] / IN_;  // N samples

    kan_setup_kernel<<<NSPL, 32>>>(l1_coeffs, l1_kd, op_alpha, gumbel,
                                   l2_coeffs, l2_kd, base_off);
    int threads = 256;
    int blocks = (n + threads - 1) / threads;
    kan_main_kernel<<<blocks, threads>>>((const float4*)x, out, n);
}

// round 7
// speedup vs baseline: 1.0861x; 1.0861x over previous
#include <cuda_runtime.h>
#include <math.h>

// ----------------------------------------------------------------------------
// UnifiedKAN via uniform-bucket piecewise cubics (no interval search).
// Each of the 20 splines is tabulated as NB=128 cubics on uniform buckets of
// [-1,1] (centered monomial, Chebyshev fit nodes). Main kernel: bucket index
// and center are pure arithmetic (shared across splines per value); each
// spline eval = ONE LDS.128 + Horner. Setup: 20 blocks x NB threads, one
// bucket fit per thread (4 exact reference-spline evals + Newton fit).
// ----------------------------------------------------------------------------

#define GRID_ 5
#define IN_ 4
#define HID_ 4
#define NSPL 20
#define NB 128                    // uniform buckets over [-1,1]
#define HB (2.0f / NB)            // bucket width = 1/64
#define RWB ((float)NB / 2.0f)    // 64 = 1/HB

__device__ float4 g_buckets[NSPL * NB];  // 40 KB: {c0,c1,c2,c3} per bucket
__device__ float g_w[12];                // [0..7] softmax weights, [8] base

// Reference float32 Cox-de Boor (first 8 basis fns), denominators replaced by
// precomputed reciprocals rc[] (0 when den<=1e-8).
__device__ __forceinline__ float eval_ref_spline(float x, const float* kn /*13*/,
                                                 const float* rc /*33*/,
                                                 const float* cf /*8*/) {
    float b[12];
    #pragma unroll
    for (int j = 0; j < 12; j++)
        b[j] = (x >= kn[j] && x < kn[j + 1]) ? 1.0f : 0.0f;
    if (x == kn[12]) b[11] += 1.0f;
    const int off[4] = {0, 0, 12, 23};
    #pragma unroll
    for (int d = 1; d <= 3; d++) {
        int n = 12 - d;
        const float* r = rc + off[d];
        #pragma unroll
        for (int j = 0; j < 11; j++) {
            if (j >= n) break;
            float t1 = (x - kn[j]) * r[j] * b[j];
            float t2 = (kn[d + 1 + j] - x) * r[j + 1] * b[j + 1];
            b[j] = t1 + t2;  // in-place ascending: b[j+1] still old value
        }
    }
    float s = 0.0f;
    #pragma unroll
    for (int j = 0; j < 8; j++) s += b[j] * cf[j];
    return s;
}

// One block per spline, NB threads = one bucket per thread.
__global__ void kan_setup_kernel(const float* __restrict__ l1_coeffs,
                                 const float* __restrict__ l1_kd,
                                 const float* __restrict__ op_alpha,
                                 const float* __restrict__ gumbel,
                                 const float* __restrict__ l2_coeffs,
                                 const float* __restrict__ l2_kd,
                                 const float* __restrict__ base_offset) {
    __shared__ float s_rc[33];

    int s = blockIdx.x;
    int lane = threadIdx.x;
    const float* kd = (s < 16) ? (l1_kd + s * (GRID_ + 1)) : (l2_kd + (s - 16) * (GRID_ + 1));
    const float* cf = (s < 16) ? (l1_coeffs + s * 8) : (l2_coeffs + (s - 16) * 8);

    // Every thread redundantly computes the 13-knot vector (lockstep, cheap).
    float d[GRID_ + 1];
    float dsum = 0.0f;
    #pragma unroll
    for (int k = 0; k < GRID_ + 1; k++) {
        float v = kd[k];
        d[k] = fmaxf(v, 0.0f) + log1pf(expf(-fabsf(v)));  // stable softplus
        dsum += d[k];
    }
    float kn[13];
    kn[0] = kn[1] = kn[2] = kn[3] = -1.0f;
    float cum = 0.0f;
    #pragma unroll
    for (int k = 0; k < 5; k++) {
        cum += d[k] / dsum * 2.0f;
        kn[4 + k] = -1.0f + cum;
    }
    kn[9] = kn[10] = kn[11] = kn[12] = 1.0f;

    // Reciprocals of the 33 knot-difference denominators (masked to 0).
    if (lane < 33) {
        int t = lane, dd, j;
        if (t < 12)      { dd = 1; j = t; }
        else if (t < 23) { dd = 2; j = t - 12; }
        else             { dd = 3; j = t - 23; }
        float den = kn[dd + j] - kn[j];
        s_rc[t] = (den > 1e-8f) ? 1.0f / den : 0.0f;
    }
    if (s == 0) {
        if (lane >= 40 && lane < 40 + HID_) {
            int h = lane - 40;
            float a0 = op_alpha[h * 2 + 0] + gumbel[h * 2 + 0];
            float a1 = op_alpha[h * 2 + 1] + gumbel[h * 2 + 1];
            float mx = fmaxf(a0, a1);
            float e0 = expf(a0 - mx), e1 = expf(a1 - mx);
            float inv = 1.0f / (e0 + e1);
            g_w[h * 2 + 0] = e0 * inv;
            g_w[h * 2 + 1] = e1 * inv;
        }
        if (lane == 44) g_w[8] = base_offset[0];
    }
    __syncthreads();

    // Fit cubic on bucket [lo, lo+HB) at 4 Chebyshev nodes (in normalized
    // s = (x - m)/HB, nodes s_k = 0.5*cos((2k+1)*pi/8)).
    const float sn0 = -0.4619397663f, sn1 = -0.1913417162f,
                sn2 =  0.1913417162f, sn3 =  0.4619397663f;
    int b = lane;
    float lo = -1.0f + (float)b * HB;
    float m  = lo + 0.5f * HB;
    float f0 = eval_ref_spline(fmaf(sn0, HB, m), kn, s_rc, cf);
    float f1 = eval_ref_spline(fmaf(sn1, HB, m), kn, s_rc, cf);
    float f2 = eval_ref_spline(fmaf(sn2, HB, m), kn, s_rc, cf);
    float f3 = eval_ref_spline(fmaf(sn3, HB, m), kn, s_rc, cf);

    // Newton divided differences in s (node spacings are compile-time consts).
    float c01   = (f1 - f0) * (1.0f / (sn1 - sn0));
    float c12   = (f2 - f1) * (1.0f / (sn2 - sn1));
    float c23   = (f3 - f2) * (1.0f / (sn3 - sn2));
    float c012  = (c12 - c01) * (1.0f / (sn2 - sn0));
    float c123  = (c23 - c12) * (1.0f / (sn3 - sn1));
    float c0123 = (c123 - c012) * (1.0f / (sn3 - sn0));
    // Expand Newton form ((c0123*(s-sn2)+c012)*(s-sn1)+c01)*(s-sn0)+f0
    float p0 = c0123, p1 = 0.0f, p2 = 0.0f, p3 = 0.0f;
    const float nodes[3] = {sn2, sn1, sn0};
    const float adds[3]  = {c012, c01, f0};
    #pragma unroll
    for (int st = 0; st < 3; st++) {
        float vv = nodes[st];
        float q3 = p2, q2 = p1, q1 = p0;
        float q0 = adds[st] - vv * p0;
        q1 -= vv * p1; q2 -= vv * p2; q3 -= vv * p3;
        p0 = q0; p1 = q1; p2 = q2; p3 = q3;
    }
    // Scale to t = x - m coordinate: c_k = p_k * RWB^k.
    float4 c;
    c.x = p0;
    c.y = p1 * RWB;
    c.z = p2 * (RWB * RWB);
    c.w = p3 * (RWB * RWB * RWB);
    g_buckets[s * NB + b] = c;
}

__global__ void __launch_bounds__(512) kan_main_kernel(const float4* __restrict__ x,
                                                       float* __restrict__ out, int n) {
    __shared__ __align__(16) float4 s_coef[NSPL * NB];  // 40 KB
    __shared__ float s_w[12];
    for (int k = threadIdx.x; k < NSPL * NB; k += blockDim.x) s_coef[k] = g_buckets[k];
    if (threadIdx.x < 12) s_w[threadIdx.x] = g_w[threadIdx.x];
    __syncthreads();

    int stride = gridDim.x * blockDim.x;
    for (int i0 = blockIdx.x * blockDim.x + threadIdx.x; i0 < n; i0 += stride) {
        float4 xv = x[i0];
        float xi[4] = {xv.x, xv.y, xv.z, xv.w};
        int bi[4];
        float ti[4];
        #pragma unroll
        for (int i = 0; i < 4; i++) {
            float f = fminf(fmaf(xi[i], RWB, RWB), (float)(NB - 1));  // x in [-1,1]
            int b = (int)f;
            bi[i] = b;
            ti[i] = xi[i] - fmaf((float)b + 0.5f, HB, -1.0f);
        }

        float acc = s_w[8];
        #pragma unroll
        for (int h = 0; h < HID_; h++) {
            float sum = 0.0f, prod = 1.0f;
            #pragma unroll
            for (int i = 0; i < IN_; i++) {
                float4 c = s_coef[(h * IN_ + i) * NB + bi[i]];
                float t = ti[i];
                float v = fmaf(fmaf(fmaf(c.w, t, c.z), t, c.y), t, c.x);
                sum += v;
                prod *= fminf(fmaxf(v, -5.0f), 5.0f);
            }
            float hid = s_w[h * 2 + 0] * sum + s_w[h * 2 + 1] * prod;
            // Layer-2: bucket by arithmetic; mask out-of-range [-1,1].
            float f = fminf(fmaxf(fmaf(hid, RWB, RWB), 0.0f), (float)(NB - 1));
            int b2 = (int)f;
            float t2 = hid - fmaf((float)b2 + 0.5f, HB, -1.0f);
            float4 c2 = s_coef[(16 + h) * NB + b2];
            float v2 = fmaf(fmaf(fmaf(c2.w, t2, c2.z), t2, c2.y), t2, c2.x);
            bool in_range = (hid >= -1.0f) && (hid <= 1.0f);
            acc += in_range ? v2 : 0.0f;
        }
        out[i0] = acc;
    }
}

extern "C" void kernel_launch(void* const* d_in, const int* in_sizes, int n_in,
                              void* d_out, int out_size) {
    const float* x          = (const float*)d_in[0];
    const float* l1_coeffs  = (const float*)d_in[1];
    const float* l1_kd      = (const float*)d_in[2];
    const float* op_alpha   = (const float*)d_in[3];
    const float* gumbel     = (const float*)d_in[4];
    const float* l2_coeffs  = (const float*)d_in[5];
    const float* l2_kd      = (const float*)d_in[6];
    const float* base_off   = (const float*)d_in[7];
    float* out = (float*)d_out;

    int n = in_sizes[0] / IN_;  // N samples

    kan_setup_kernel<<<NSPL, NB>>>(l1_coeffs, l1_kd, op_alpha, gumbel,
                                   l2_coeffs, l2_kd, base_off);
    // 4 blocks/SM x 148 SMs = 592 blocks x 512 threads, grid-stride.
    kan_main_kernel<<<592, 512>>>((const float4*)x, out, n);
}